// round 2
// baseline (speedup 1.0000x reference)
#include <cuda_runtime.h>
#include <math.h>

// Problem constants (fixed by the dataset)
#define BB 16
#define SS 1024
#define DD 512
#define HH 4

// GEMM tiling
#define BM 128
#define BN 128
#define BKK 16
#define SPAD 4
#define NTHREADS 256

// Scratch (static device globals; allocation inside kernel_launch is forbidden)
__device__ __align__(16) float g_x[(size_t)BB * SS * DD];          // 32 MB
__device__ __align__(16) float g_v[(size_t)BB * SS * DD];          // 32 MB
__device__ __align__(16) float g_attn[(size_t)BB * SS * SS];       // 64 MB
__device__ __align__(16) float g_invnorm[BB * SS];

// ---------------------------------------------------------------------------
// Shared fp32 GEMM mainloop.
//   A: row-major, K contiguous (lda), pre-offset to this block's row tile.
//   B: if BKC (==true, "NT"): row-major [N,K], K contiguous, pre-offset to col tile.
//      else ("NN"):          row-major [K,N], N contiguous, pre-offset by n0 columns.
//   All dims assumed multiples of tile sizes (true for this problem).
// ---------------------------------------------------------------------------
template <bool BKC>
__device__ __forceinline__ void gemm_main(const float* __restrict__ A, int lda,
                                          const float* __restrict__ Bm, int ldb,
                                          int K, float (&acc)[8][8]) {
    __shared__ float As[BKK * (BM + SPAD)];
    __shared__ float Bs[BKK * (BN + SPAD)];

    const int tid = threadIdx.x;
    const int tx = tid & 15;
    const int ty = tid >> 4;

#pragma unroll
    for (int i = 0; i < 8; i++)
#pragma unroll
        for (int j = 0; j < 8; j++) acc[i][j] = 0.f;

    for (int kt = 0; kt < K; kt += BKK) {
        // --- load A tile: 128 rows x 16 k, transposed into As[k][m] ---
#pragma unroll
        for (int c0 = 0; c0 < 2; c0++) {
            int c = tid + c0 * NTHREADS;
            int row = c >> 2, seg = c & 3;
            float4 v = *(const float4*)(A + (size_t)row * lda + kt + seg * 4);
            As[(seg * 4 + 0) * (BM + SPAD) + row] = v.x;
            As[(seg * 4 + 1) * (BM + SPAD) + row] = v.y;
            As[(seg * 4 + 2) * (BM + SPAD) + row] = v.z;
            As[(seg * 4 + 3) * (BM + SPAD) + row] = v.w;
        }
        // --- load B tile into Bs[k][n] ---
        if (BKC) {
#pragma unroll
            for (int c0 = 0; c0 < 2; c0++) {
                int c = tid + c0 * NTHREADS;
                int row = c >> 2, seg = c & 3;  // row = n index
                float4 v = *(const float4*)(Bm + (size_t)row * ldb + kt + seg * 4);
                Bs[(seg * 4 + 0) * (BN + SPAD) + row] = v.x;
                Bs[(seg * 4 + 1) * (BN + SPAD) + row] = v.y;
                Bs[(seg * 4 + 2) * (BN + SPAD) + row] = v.z;
                Bs[(seg * 4 + 3) * (BN + SPAD) + row] = v.w;
            }
        } else {
#pragma unroll
            for (int c0 = 0; c0 < 2; c0++) {
                int c = tid + c0 * NTHREADS;
                int kr = c >> 5, seg = c & 31;
                float4 v = *(const float4*)(Bm + (size_t)(kt + kr) * ldb + seg * 4);
                *(float4*)(&Bs[kr * (BN + SPAD) + seg * 4]) = v;
            }
        }
        __syncthreads();

#pragma unroll
        for (int kk = 0; kk < BKK; kk++) {
            float4 a0 = *(const float4*)(&As[kk * (BM + SPAD) + ty * 8]);
            float4 a1 = *(const float4*)(&As[kk * (BM + SPAD) + ty * 8 + 4]);
            float4 b0 = *(const float4*)(&Bs[kk * (BN + SPAD) + tx * 8]);
            float4 b1 = *(const float4*)(&Bs[kk * (BN + SPAD) + tx * 8 + 4]);
            float a[8] = {a0.x, a0.y, a0.z, a0.w, a1.x, a1.y, a1.z, a1.w};
            float b[8] = {b0.x, b0.y, b0.z, b0.w, b1.x, b1.y, b1.z, b1.w};
#pragma unroll
            for (int i = 0; i < 8; i++)
#pragma unroll
                for (int j = 0; j < 8; j++) acc[i][j] = fmaf(a[i], b[j], acc[i][j]);
        }
        __syncthreads();
    }
}

// ---------------------------------------------------------------------------
// K1: attn_raw[b,q,k] = mask * (x[b,q]·x[b,k]) / sqrt(D)
//     mask keeps (k > q) OR (event_type[b,k] == 0)
//     event_type is int32 on device (JAX x64 disabled).
// ---------------------------------------------------------------------------
__global__ __launch_bounds__(NTHREADS, 2) void k_qk(const int* __restrict__ et) {
    const int b = blockIdx.z;
    const int q0 = blockIdx.y * BM;
    const int k0 = blockIdx.x * BN;
    const float* A = g_x + (size_t)b * SS * DD + (size_t)q0 * DD;
    const float* Bm = g_x + (size_t)b * SS * DD + (size_t)k0 * DD;

    float acc[8][8];
    gemm_main<true>(A, DD, Bm, DD, DD, acc);

    const int tx = threadIdx.x & 15;
    const int ty = threadIdx.x >> 4;
    const float invtemp = rsqrtf((float)DD);

    // preload pad flags for this thread's 8 key columns
    bool pad[8];
#pragma unroll
    for (int j = 0; j < 8; j++) pad[j] = (et[b * SS + k0 + tx * 8 + j] == 0);

#pragma unroll
    for (int i = 0; i < 8; i++) {
        const int q = q0 + ty * 8 + i;
        float* row = g_attn + (size_t)b * SS * SS + (size_t)q * SS + k0 + tx * 8;
#pragma unroll
        for (int j = 0; j < 8; j++) {
            const int kc = k0 + tx * 8 + j;
            const bool keep = (kc > q) || pad[j];
            row[j] = keep ? acc[i][j] * invtemp : 0.f;
        }
    }
}

// ---------------------------------------------------------------------------
// K2: g_invnorm[b*S+q] = 1 / max(||attn_raw[b,q,:]||_2 , 1e-5)
// ---------------------------------------------------------------------------
__global__ void k_norm() {
    __shared__ float red[NTHREADS];
    const int row = blockIdx.x;  // b*S + q
    const float4* p = (const float4*)(g_attn + (size_t)row * SS);
    // 1024 elems = 256 float4; one per thread
    float4 v = p[threadIdx.x];
    float ss = fmaf(v.x, v.x, fmaf(v.y, v.y, fmaf(v.z, v.z, v.w * v.w)));
    red[threadIdx.x] = ss;
    __syncthreads();
    for (int s = 128; s > 0; s >>= 1) {
        if (threadIdx.x < s) red[threadIdx.x] += red[threadIdx.x + s];
        __syncthreads();
    }
    if (threadIdx.x == 0) g_invnorm[row] = 1.f / fmaxf(sqrtf(red[0]), 1e-5f);
}

// ---------------------------------------------------------------------------
// K3: v[m,e] = elu( sum_d x[m,d] * W[e,d] + bias[e] ),  m in [0, B*S)
// ---------------------------------------------------------------------------
__global__ __launch_bounds__(NTHREADS, 2) void k_v(const float* __restrict__ W,
                                                   const float* __restrict__ bias) {
    const int m0 = blockIdx.y * BM;
    const int n0 = blockIdx.x * BN;
    const float* A = g_x + (size_t)m0 * DD;
    const float* Bm = W + (size_t)n0 * DD;

    float acc[8][8];
    gemm_main<true>(A, DD, Bm, DD, DD, acc);

    const int tx = threadIdx.x & 15;
    const int ty = threadIdx.x >> 4;

    float bj[8];
#pragma unroll
    for (int j = 0; j < 8; j++) bj[j] = bias[n0 + tx * 8 + j];

#pragma unroll
    for (int i = 0; i < 8; i++) {
        float* row = g_v + (size_t)(m0 + ty * 8 + i) * DD + n0 + tx * 8;
#pragma unroll
        for (int j = 0; j < 8; j++) {
            float val = acc[i][j] + bj[j];
            row[j] = (val > 0.f) ? val : expm1f(val);
        }
    }
}

// ---------------------------------------------------------------------------
// K4: xnew[b,q,d] = invnorm[b,q] * sum_k attn_raw[b,q,k] * v[b,k,d]
//     g_x <- xnew ; out += xnew
// ---------------------------------------------------------------------------
__global__ __launch_bounds__(NTHREADS, 2) void k_av(float* __restrict__ out) {
    const int b = blockIdx.z;
    const int q0 = blockIdx.y * BM;
    const int n0 = blockIdx.x * BN;
    const float* A = g_attn + (size_t)b * SS * SS + (size_t)q0 * SS;
    const float* Bm = g_v + (size_t)b * SS * DD + n0;

    float acc[8][8];
    gemm_main<false>(A, SS, Bm, DD, SS, acc);

    const int tx = threadIdx.x & 15;
    const int ty = threadIdx.x >> 4;

#pragma unroll
    for (int i = 0; i < 8; i++) {
        const int q = q0 + ty * 8 + i;
        const float invn = g_invnorm[b * SS + q];
        const size_t base = (size_t)b * SS * DD + (size_t)q * DD + n0 + tx * 8;
#pragma unroll
        for (int j = 0; j < 8; j++) {
            const float val = acc[i][j] * invn;
            g_x[base + j] = val;
            out[base + j] += val;
        }
    }
}

// ---------------------------------------------------------------------------
__global__ void copy_in4(const float4* __restrict__ in) {
    size_t i = (size_t)blockIdx.x * blockDim.x + threadIdx.x;
    ((float4*)g_x)[i] = in[i];
}

extern "C" void kernel_launch(void* const* d_in, const int* in_sizes, int n_in,
                              void* d_out, int out_size) {
    const float* x_in = (const float*)d_in[0];   // output [B,S,D] fp32
    // d_in[1] = local_cor (unused by reference)
    const int* et = (const int*)d_in[2];         // event_type [B,S] int32
    const float* W = (const float*)d_in[3];      // [H,D,D] fp32
    const float* bias = (const float*)d_in[4];   // [H,D] fp32
    float* out = (float*)d_out;

    const size_t n_x = (size_t)BB * SS * DD;  // 8,388,608

    cudaMemsetAsync(out, 0, n_x * sizeof(float), 0);
    copy_in4<<<(unsigned)(n_x / 4 / NTHREADS), NTHREADS>>>((const float4*)x_in);

    const dim3 grid_qk(SS / BN, SS / BM, BB);       // (8, 8, 16)
    const dim3 grid_v(DD / BN, (BB * SS) / BM, 1);  // (4, 128)
    const dim3 grid_av(DD / BN, SS / BM, BB);       // (4, 8, 16)

    for (int h = 0; h < HH; h++) {
        k_qk<<<grid_qk, NTHREADS>>>(et);
        k_norm<<<BB * SS, NTHREADS>>>();
        k_v<<<grid_v, NTHREADS>>>(W + (size_t)h * DD * DD, bias + (size_t)h * DD);
        k_av<<<grid_av, NTHREADS>>>(out);
    }
}

// round 3
// speedup vs baseline: 1.3663x; 1.3663x over previous
#include <cuda_runtime.h>
#include <math.h>

// Problem constants (fixed by the dataset)
#define BB 16
#define SS 1024
#define DD 512
#define HH 4

// GEMM tiling
#define BM 128
#define BN 128
#define BKK 16
#define SPAD 4
#define NTHREADS 256

// Scratch (static device globals; allocation inside kernel_launch is forbidden)
__device__ __align__(16) float g_x[(size_t)BB * SS * DD];          // 32 MB
__device__ __align__(16) float g_v[(size_t)BB * SS * DD];          // 32 MB
__device__ __align__(16) float g_attn[(size_t)BB * SS * SS];       // 64 MB
__device__ __align__(16) float g_norm2[BB * SS];
__device__ int g_padchunk[BB * (SS / BKK)];  // any pad in 16-chunk [b][c]
__device__ int g_padblk[BB * (SS / BN)];     // any pad in 128-block [b][kb]

// ---------------------------------------------------------------------------
// Tile load/store helpers (256 threads; tiles 128 x 16)
// ---------------------------------------------------------------------------
__device__ __forceinline__ void ld_nt(const float* __restrict__ P, int ld, int kt,
                                      float4 (&r)[2]) {
    const int tid = threadIdx.x;
#pragma unroll
    for (int c0 = 0; c0 < 2; c0++) {
        int c = tid + c0 * NTHREADS;
        int row = c >> 2, seg = c & 3;
        r[c0] = *(const float4*)(P + (size_t)row * ld + kt + seg * 4);
    }
}
__device__ __forceinline__ void st_nt(float* S, const float4 (&r)[2]) {
    const int tid = threadIdx.x;
#pragma unroll
    for (int c0 = 0; c0 < 2; c0++) {
        int c = tid + c0 * NTHREADS;
        int row = c >> 2, seg = c & 3;
        S[(seg * 4 + 0) * (BM + SPAD) + row] = r[c0].x;
        S[(seg * 4 + 1) * (BM + SPAD) + row] = r[c0].y;
        S[(seg * 4 + 2) * (BM + SPAD) + row] = r[c0].z;
        S[(seg * 4 + 3) * (BM + SPAD) + row] = r[c0].w;
    }
}
__device__ __forceinline__ void ld_nn(const float* __restrict__ P, int ld, int kt,
                                      float4 (&r)[2]) {
    const int tid = threadIdx.x;
#pragma unroll
    for (int c0 = 0; c0 < 2; c0++) {
        int c = tid + c0 * NTHREADS;
        int kr = c >> 5, seg = c & 31;
        r[c0] = *(const float4*)(P + (size_t)(kt + kr) * ld + seg * 4);
    }
}
__device__ __forceinline__ void st_nn(float* S, const float4 (&r)[2]) {
    const int tid = threadIdx.x;
#pragma unroll
    for (int c0 = 0; c0 < 2; c0++) {
        int c = tid + c0 * NTHREADS;
        int kr = c >> 5, seg = c & 31;
        *(float4*)(&S[kr * (BN + SPAD) + seg * 4]) = r[c0];
    }
}

__device__ __forceinline__ void compute_step(const float* As, const float* Bs,
                                             float (&acc)[8][8]) {
    const int tx = threadIdx.x & 15;
    const int ty = threadIdx.x >> 4;
#pragma unroll
    for (int kk = 0; kk < BKK; kk++) {
        float4 a0 = *(const float4*)(&As[kk * (BM + SPAD) + ty * 8]);
        float4 a1 = *(const float4*)(&As[kk * (BM + SPAD) + ty * 8 + 4]);
        float4 b0 = *(const float4*)(&Bs[kk * (BN + SPAD) + tx * 8]);
        float4 b1 = *(const float4*)(&Bs[kk * (BN + SPAD) + tx * 8 + 4]);
        float a[8] = {a0.x, a0.y, a0.z, a0.w, a1.x, a1.y, a1.z, a1.w};
        float b[8] = {b0.x, b0.y, b0.z, b0.w, b1.x, b1.y, b1.z, b1.w};
#pragma unroll
        for (int i = 0; i < 8; i++)
#pragma unroll
            for (int j = 0; j < 8; j++) acc[i][j] = fmaf(a[i], b[j], acc[i][j]);
    }
}

// NT x NT pipelined GEMM over contiguous K range
__device__ __forceinline__ void gemm_nt(const float* __restrict__ A, int lda,
                                        const float* __restrict__ Bm, int ldb,
                                        int K, float (&acc)[8][8],
                                        float* As, float* Bs) {
#pragma unroll
    for (int i = 0; i < 8; i++)
#pragma unroll
        for (int j = 0; j < 8; j++) acc[i][j] = 0.f;

    float4 ra[2], rb[2];
    ld_nt(A, lda, 0, ra);
    ld_nt(Bm, ldb, 0, rb);
    for (int kt = 0; kt < K; kt += BKK) {
        st_nt(As, ra);
        st_nt(Bs, rb);
        __syncthreads();
        if (kt + BKK < K) {
            ld_nt(A, lda, kt + BKK, ra);
            ld_nt(Bm, ldb, kt + BKK, rb);
        }
        compute_step(As, Bs, acc);
        __syncthreads();
    }
}

// ---------------------------------------------------------------------------
// init kernels
// ---------------------------------------------------------------------------
__global__ void k_zero4(float4* p) {
    p[(size_t)blockIdx.x * blockDim.x + threadIdx.x] = make_float4(0.f, 0.f, 0.f, 0.f);
}
__global__ void k_zero_sym_attn() {
    ((float4*)g_attn)[(size_t)blockIdx.x * blockDim.x + threadIdx.x] =
        make_float4(0.f, 0.f, 0.f, 0.f);
}
__global__ void k_zero_norm2() {
    ((float4*)g_norm2)[blockIdx.x * blockDim.x + threadIdx.x] =
        make_float4(0.f, 0.f, 0.f, 0.f);
}
__global__ void copy_in4(const float4* __restrict__ in) {
    size_t i = (size_t)blockIdx.x * blockDim.x + threadIdx.x;
    ((float4*)g_x)[i] = in[i];
}
__global__ void k_flags(const int* __restrict__ et) {
    int idx = blockIdx.x * blockDim.x + threadIdx.x;  // BB*64 = 1024
    if (idx < BB * (SS / BKK)) {
        int b = idx >> 6, c = idx & 63;
        int any = 0;
        for (int i = 0; i < BKK; i++) any |= (et[b * SS + c * BKK + i] == 0);
        g_padchunk[idx] = any;
    }
}
__global__ void k_blkflags() {
    int idx = threadIdx.x;  // BB*8 = 128
    if (idx < BB * (SS / BN)) {
        int b = idx >> 3, kb = idx & 7;
        int any = 0;
        for (int c = 0; c < 8; c++) any |= g_padchunk[b * 64 + kb * 8 + c];
        g_padblk[idx] = any;
    }
}

// ---------------------------------------------------------------------------
// K1: attn[b,q,k] = mask * (x[b,q]·x[b,k]) / sqrt(D);  fused row sum-of-squares.
//     mask keeps (k > q) OR (et[b,k] == 0). Below-diag no-pad blocks skipped
//     entirely (g_attn pre-zeroed once).
// ---------------------------------------------------------------------------
__global__ __launch_bounds__(NTHREADS, 2) void k_qk(const int* __restrict__ et) {
    const int b = blockIdx.z;
    const int q0 = blockIdx.y * BM;
    const int k0 = blockIdx.x * BN;

    const bool below = (k0 < q0);
    if (below && !g_padblk[b * 8 + (k0 >> 7)]) return;  // all-zero tile
    const bool above = (k0 > q0);

    __shared__ float As[BKK * (BM + SPAD)];
    __shared__ float Bs[BKK * (BN + SPAD)];

    const float* A = g_x + (size_t)b * SS * DD + (size_t)q0 * DD;
    const float* Bm = g_x + (size_t)b * SS * DD + (size_t)k0 * DD;

    float acc[8][8];
    gemm_nt(A, DD, Bm, DD, DD, acc, As, Bs);

    const int tx = threadIdx.x & 15;
    const int ty = threadIdx.x >> 4;
    const float invtemp = rsqrtf((float)DD);

    bool pad[8];
#pragma unroll
    for (int j = 0; j < 8; j++) pad[j] = (et[b * SS + k0 + tx * 8 + j] == 0);

#pragma unroll
    for (int i = 0; i < 8; i++) {
        const int q = q0 + ty * 8 + i;
        float* row = g_attn + (size_t)b * SS * SS + (size_t)q * SS + k0 + tx * 8;
        float sq = 0.f;
#pragma unroll
        for (int j = 0; j < 8; j++) {
            const int kc = k0 + tx * 8 + j;
            const bool keep = above || (kc > q) || pad[j];
            const float val = keep ? acc[i][j] * invtemp : 0.f;
            row[j] = val;
            sq = fmaf(val, val, sq);
        }
        // reduce over the 16 tx lanes (stay within 16-lane half-warps)
#pragma unroll
        for (int o = 8; o > 0; o >>= 1) sq += __shfl_xor_sync(0xffffffffu, sq, o);
        if (tx == 0) atomicAdd(&g_norm2[b * SS + q], sq);
    }
}

// ---------------------------------------------------------------------------
// K3: v[m,e] = elu( x[m,:]·W[e,:] + bias[e] )
// ---------------------------------------------------------------------------
__global__ __launch_bounds__(NTHREADS, 2) void k_v(const float* __restrict__ W,
                                                   const float* __restrict__ bias) {
    __shared__ float As[BKK * (BM + SPAD)];
    __shared__ float Bs[BKK * (BN + SPAD)];

    const int m0 = blockIdx.y * BM;
    const int n0 = blockIdx.x * BN;
    const float* A = g_x + (size_t)m0 * DD;
    const float* Bm = W + (size_t)n0 * DD;

    float acc[8][8];
    gemm_nt(A, DD, Bm, DD, DD, acc, As, Bs);

    const int tx = threadIdx.x & 15;
    const int ty = threadIdx.x >> 4;

    float bj[8];
#pragma unroll
    for (int j = 0; j < 8; j++) bj[j] = bias[n0 + tx * 8 + j];

#pragma unroll
    for (int i = 0; i < 8; i++) {
        float* row = g_v + (size_t)(m0 + ty * 8 + i) * DD + n0 + tx * 8;
#pragma unroll
        for (int j = 0; j < 8; j++) {
            float val = acc[i][j] + bj[j];
            row[j] = (val > 0.f) ? val : expm1f(val);
        }
    }
}

// ---------------------------------------------------------------------------
// K4: xnew[b,q,d] = invnorm[b,q] * sum_k attn[b,q,k] * v[b,k,d]
//     Skips K-chunks below the diagonal band unless they contain a pad column.
// ---------------------------------------------------------------------------
__global__ __launch_bounds__(NTHREADS, 2) void k_av(float* __restrict__ out) {
    __shared__ float As[BKK * (BM + SPAD)];
    __shared__ float Bs[BKK * (BN + SPAD)];

    const int b = blockIdx.z;
    const int q0 = blockIdx.y * BM;
    const int n0 = blockIdx.x * BN;
    const float* A = g_attn + (size_t)b * SS * SS + (size_t)q0 * SS;
    const float* Bm = g_v + (size_t)b * SS * DD + n0;
    const int* pc = g_padchunk + b * (SS / BKK);

    float acc[8][8];
#pragma unroll
    for (int i = 0; i < 8; i++)
#pragma unroll
        for (int j = 0; j < 8; j++) acc[i][j] = 0.f;

    // first active chunk
    int kt = 0;
    while (kt < q0 && !pc[kt >> 4]) kt += BKK;

    float4 ra[2], rb[2];
    ld_nt(A, SS, kt, ra);
    ld_nn(Bm, DD, kt, rb);
    while (kt < SS) {
        int ktn = kt + BKK;
        while (ktn < q0 && !pc[ktn >> 4]) ktn += BKK;
        st_nt(As, ra);
        st_nn(Bs, rb);
        __syncthreads();
        if (ktn < SS) {
            ld_nt(A, SS, ktn, ra);
            ld_nn(Bm, DD, ktn, rb);
        }
        compute_step(As, Bs, acc);
        __syncthreads();
        kt = ktn;
    }

    const int tx = threadIdx.x & 15;
    const int ty = threadIdx.x >> 4;

#pragma unroll
    for (int i = 0; i < 8; i++) {
        const int q = q0 + ty * 8 + i;
        const float invn = 1.f / fmaxf(sqrtf(g_norm2[b * SS + q]), 1e-5f);
        const size_t base = (size_t)b * SS * DD + (size_t)q * DD + n0 + tx * 8;
#pragma unroll
        for (int j = 0; j < 8; j++) {
            const float val = acc[i][j] * invn;
            g_x[base + j] = val;
            out[base + j] += val;
        }
    }
}

// ---------------------------------------------------------------------------
extern "C" void kernel_launch(void* const* d_in, const int* in_sizes, int n_in,
                              void* d_out, int out_size) {
    const float* x_in = (const float*)d_in[0];   // output [B,S,D] fp32
    // d_in[1] = local_cor (unused by reference)
    const int* et = (const int*)d_in[2];         // event_type [B,S] int32
    const float* W = (const float*)d_in[3];      // [H,D,D] fp32
    const float* bias = (const float*)d_in[4];   // [H,D] fp32
    float* out = (float*)d_out;

    const size_t n_x = (size_t)BB * SS * DD;  // 8,388,608

    cudaMemsetAsync(out, 0, n_x * sizeof(float), 0);
    copy_in4<<<(unsigned)(n_x / 4 / NTHREADS), NTHREADS>>>((const float4*)x_in);
    // zero attn once (skipped below-diag tiles stay zero across heads)
    k_zero_sym_attn<<<(unsigned)((size_t)BB * SS * SS / 4 / NTHREADS), NTHREADS>>>();
    k_flags<<<4, 256>>>(et);
    k_blkflags<<<1, 128>>>();

    const dim3 grid_qk(SS / BN, SS / BM, BB);       // (8, 8, 16)
    const dim3 grid_v(DD / BN, (BB * SS) / BM, 1);  // (4, 128)
    const dim3 grid_av(DD / BN, SS / BM, BB);       // (4, 8, 16)

    for (int h = 0; h < HH; h++) {
        k_zero_norm2<<<BB * SS / 4 / NTHREADS, NTHREADS>>>();
        k_qk<<<grid_qk, NTHREADS>>>(et);
        k_v<<<grid_v, NTHREADS>>>(W + (size_t)h * DD * DD, bias + (size_t)h * DD);
        k_av<<<grid_av, NTHREADS>>>(out);
    }
}

// round 7
// speedup vs baseline: 3.0607x; 2.2401x over previous
#include <cuda_runtime.h>
#include <cuda_bf16.h>
#include <math.h>
#include <stdint.h>

// Problem constants
#define BB 16
#define SS 1024
#define DD 512
#define HH 4
#define NTHR 256

// smem staging: per stage 4 tiles (A hi/lo 128x(32+8)bf16, B hi/lo)
#define ST_SZ  40960
#define OFF_AH 0
#define OFF_AL 10240
#define OFF_BH 20480
#define OFF_BL 30720
#define SMEM_SZ (2 * ST_SZ)

#define STRA 80    // bytes per A/B-NT smem row (40 bf16)
#define STRB 272   // bytes per B-NN smem row (136 bf16)

// ---------------- device scratch ----------------
__device__ __align__(16) __nv_bfloat16 g_x_hi[(size_t)BB*SS*DD];
__device__ __align__(16) __nv_bfloat16 g_x_lo[(size_t)BB*SS*DD];
__device__ __align__(16) __nv_bfloat16 g_v_hi[(size_t)BB*SS*DD];
__device__ __align__(16) __nv_bfloat16 g_v_lo[(size_t)BB*SS*DD];
__device__ __align__(16) __nv_bfloat16 g_attn_hi[(size_t)BB*SS*SS];
__device__ __align__(16) __nv_bfloat16 g_attn_lo[(size_t)BB*SS*SS];
__device__ __align__(16) __nv_bfloat16 g_w_hi[(size_t)HH*DD*DD];
__device__ __align__(16) __nv_bfloat16 g_w_lo[(size_t)HH*DD*DD];
__device__ float g_norm2[BB*SS];
__device__ int g_pad32[BB*(SS/32)];
__device__ int g_padblk[BB*(SS/128)];

// ---------------- PTX helpers (sm_80-level only; harness targets plain sm_103) ----
#define CPA16(s, g) asm volatile("cp.async.cg.shared.global [%0], [%1], 16;" :: "r"(s), "l"(g))
#define CP_COMMIT() asm volatile("cp.async.commit_group;" ::: "memory")
#define CP_WAIT1()  asm volatile("cp.async.wait_group 1;" ::: "memory")
#define CP_WAIT0()  asm volatile("cp.async.wait_group 0;" ::: "memory")

#define LDSMX4(r0, r1, r2, r3, a)                                              \
    asm volatile("ldmatrix.sync.aligned.m8n8.x4.shared.b16 {%0,%1,%2,%3}, [%4];" \
                 : "=r"(r0), "=r"(r1), "=r"(r2), "=r"(r3) : "r"(a))
#define LDSMX4T(r0, r1, r2, r3, a)                                             \
    asm volatile("ldmatrix.sync.aligned.m8n8.x4.trans.shared.b16 {%0,%1,%2,%3}, [%4];" \
                 : "=r"(r0), "=r"(r1), "=r"(r2), "=r"(r3) : "r"(a))

#define MMA16816(c, a, b0v, b1v)                                               \
    asm volatile(                                                              \
        "mma.sync.aligned.m16n8k16.row.col.f32.bf16.bf16.f32 "                 \
        "{%0,%1,%2,%3}, {%4,%5,%6,%7}, {%8,%9}, {%0,%1,%2,%3};"                \
        : "+f"((c)[0]), "+f"((c)[1]), "+f"((c)[2]), "+f"((c)[3])               \
        : "r"((a)[0]), "r"((a)[1]), "r"((a)[2]), "r"((a)[3]), "r"(b0v), "r"(b1v))

// ---------------- tile loaders (256 threads) ----------------
// 128 rows x 32 bf16 (64B/row) from row-major src (ld2 = row stride bytes)
__device__ __forceinline__ void ldg_128x32(uint32_t dst, const char* src, size_t ld2, int kt) {
#pragma unroll
    for (int p = 0; p < 2; p++) {
        int i = threadIdx.x + p * NTHR;
        int row = i >> 2, seg = i & 3;
        CPA16(dst + row * STRA + seg * 16,
              src + (size_t)row * ld2 + (size_t)kt * 2 + seg * 16);
    }
}
// 32 rows x 128 bf16 (256B/row) from row-major src (rows = k), src pre-offset by n0
__device__ __forceinline__ void ldg_32x128(uint32_t dst, const char* src, size_t ld2, int kt) {
#pragma unroll
    for (int p = 0; p < 2; p++) {
        int i = threadIdx.x + p * NTHR;
        int row = i >> 4, seg = i & 15;
        CPA16(dst + row * STRB + seg * 16,
              src + (size_t)(kt + row) * ld2 + seg * 16);
    }
}

// ---------------- warp MMA compute on one staged 128x128x32 chunk ------------
// Warp layout: 8 warps = 2(m) x 4(n); warp tile 64x32; mma m16n8k16.
// C[mt][nt][4], mt 0..3 (16 rows), nt 0..3 (8 cols)
template <bool BT>
__device__ __forceinline__ void compute_chunk(uint32_t sbase, float (&C)[4][4][4]) {
    const int lane = threadIdx.x & 31;
    const int wid = threadIdx.x >> 5;
    const int wm = wid >> 2, wn = wid & 3;
#pragma unroll
    for (int ks = 0; ks < 2; ks++) {
        uint32_t ah[4][4], al[4][4];
#pragma unroll
        for (int mt = 0; mt < 4; mt++) {
            uint32_t ra = sbase + OFF_AH +
                (uint32_t)((wm * 64 + mt * 16 + (lane & 15)) * STRA + ks * 32 + (lane >> 4) * 16);
            LDSMX4(ah[mt][0], ah[mt][1], ah[mt][2], ah[mt][3], ra);
            ra += (OFF_AL - OFF_AH);
            LDSMX4(al[mt][0], al[mt][1], al[mt][2], al[mt][3], ra);
        }
        uint32_t bh[2][4], bl[2][4];
#pragma unroll
        for (int ntp = 0; ntp < 2; ntp++) {
            if (!BT) {
                uint32_t rb = sbase + OFF_BH +
                    (uint32_t)((wn * 32 + ntp * 16 + (lane >> 4) * 8 + (lane & 7)) * STRA +
                               ks * 32 + ((lane >> 3) & 1) * 16);
                LDSMX4(bh[ntp][0], bh[ntp][1], bh[ntp][2], bh[ntp][3], rb);
                rb += (OFF_BL - OFF_BH);
                LDSMX4(bl[ntp][0], bl[ntp][1], bl[ntp][2], bl[ntp][3], rb);
            } else {
                uint32_t rb = sbase + OFF_BH +
                    (uint32_t)((ks * 16 + ((lane >> 3) & 1) * 8 + (lane & 7)) * STRB +
                               (wn * 32 + ntp * 16) * 2 + (lane >> 4) * 16);
                LDSMX4T(bh[ntp][0], bh[ntp][1], bh[ntp][2], bh[ntp][3], rb);
                rb += (OFF_BL - OFF_BH);
                LDSMX4T(bl[ntp][0], bl[ntp][1], bl[ntp][2], bl[ntp][3], rb);
            }
        }
#pragma unroll
        for (int mt = 0; mt < 4; mt++)
#pragma unroll
            for (int nt = 0; nt < 4; nt++) {
                const int p = nt >> 1, j = (nt & 1) * 2;
                MMA16816(C[mt][nt], ah[mt], bh[p][j], bh[p][j + 1]);
                MMA16816(C[mt][nt], ah[mt], bl[p][j], bl[p][j + 1]);
                MMA16816(C[mt][nt], al[mt], bh[p][j], bh[p][j + 1]);
            }
    }
}

__device__ __forceinline__ void zeroC(float (&C)[4][4][4]) {
#pragma unroll
    for (int a = 0; a < 4; a++)
#pragma unroll
        for (int b = 0; b < 4; b++)
#pragma unroll
            for (int c = 0; c < 4; c++) C[a][b][c] = 0.f;
}
__device__ __forceinline__ uint32_t packsplit_hi(float v0, float v1) {
    __nv_bfloat162 h = __floats2bfloat162_rn(v0, v1);
    return *(uint32_t*)&h;
}
__device__ __forceinline__ uint32_t packsplit_lo(float v0, float v1) {
    float r0 = v0 - __bfloat162float(__float2bfloat16(v0));
    float r1 = v1 - __bfloat162float(__float2bfloat16(v1));
    __nv_bfloat162 l = __floats2bfloat162_rn(r0, r1);
    return *(uint32_t*)&l;
}

// ---------------------------------------------------------------------------
// K1: attn = mask * (Xq·Xk^T)/sqrt(D) -> bf16 hi/lo; accumulates row norm².
// ---------------------------------------------------------------------------
__global__ __launch_bounds__(NTHR, 2) void k_qk(const int* __restrict__ et) {
    const int b = blockIdx.z, q0 = blockIdx.y * 128, k0 = blockIdx.x * 128;
    const bool below = (k0 < q0);
    if (below && !g_padblk[b * 8 + (k0 >> 7)]) return;
    const bool above = (k0 > q0);

    extern __shared__ char smem[];
    const uint32_t sb = (uint32_t)__cvta_generic_to_shared(smem);

    const char* Ahi = (const char*)g_x_hi + ((size_t)b * SS + q0) * DD * 2;
    const char* Alo = (const char*)g_x_lo + ((size_t)b * SS + q0) * DD * 2;
    const char* Bhi = (const char*)g_x_hi + ((size_t)b * SS + k0) * DD * 2;
    const char* Blo = (const char*)g_x_lo + ((size_t)b * SS + k0) * DD * 2;
    const size_t ld2 = (size_t)DD * 2;

    float C[4][4][4];
    zeroC(C);

    // dense 16 k-chunks, double-buffered
    ldg_128x32(sb + OFF_AH, Ahi, ld2, 0); ldg_128x32(sb + OFF_AL, Alo, ld2, 0);
    ldg_128x32(sb + OFF_BH, Bhi, ld2, 0); ldg_128x32(sb + OFF_BL, Blo, ld2, 0);
    CP_COMMIT();
    ldg_128x32(sb + ST_SZ + OFF_AH, Ahi, ld2, 32); ldg_128x32(sb + ST_SZ + OFF_AL, Alo, ld2, 32);
    ldg_128x32(sb + ST_SZ + OFF_BH, Bhi, ld2, 32); ldg_128x32(sb + ST_SZ + OFF_BL, Blo, ld2, 32);
    CP_COMMIT();
    for (int ci = 0; ci < 16; ci++) {
        if (ci + 1 < 16) CP_WAIT1(); else CP_WAIT0();
        __syncthreads();
        compute_chunk<false>(sb + (ci & 1) * ST_SZ, C);
        __syncthreads();
        if (ci + 2 < 16) {
            uint32_t d = sb + (ci & 1) * ST_SZ;
            int kt = (ci + 2) * 32;
            ldg_128x32(d + OFF_AH, Ahi, ld2, kt); ldg_128x32(d + OFF_AL, Alo, ld2, kt);
            ldg_128x32(d + OFF_BH, Bhi, ld2, kt); ldg_128x32(d + OFF_BL, Blo, ld2, kt);
            CP_COMMIT();
        }
    }

    // epilogue
    const int lane = threadIdx.x & 31, wid = threadIdx.x >> 5;
    const int wm = wid >> 2, wn = wid & 3;
    const float invtemp = 0.04419417382415922f;  // 1/sqrt(512)

    int kg[4]; bool pad0[4], pad1[4];
#pragma unroll
    for (int nt = 0; nt < 4; nt++) {
        kg[nt] = k0 + wn * 32 + nt * 8 + (lane & 3) * 2;
        pad0[nt] = (__ldg(et + b * SS + kg[nt]) == 0);
        pad1[nt] = (__ldg(et + b * SS + kg[nt] + 1) == 0);
    }
#pragma unroll
    for (int mt = 0; mt < 4; mt++) {
        const int r0 = wm * 64 + mt * 16 + (lane >> 2);
        const int qA = q0 + r0, qB = q0 + r0 + 8;
        float sqA = 0.f, sqB = 0.f;
#pragma unroll
        for (int nt = 0; nt < 4; nt++) {
            float v0 = C[mt][nt][0] * invtemp, v1 = C[mt][nt][1] * invtemp;
            float v2 = C[mt][nt][2] * invtemp, v3 = C[mt][nt][3] * invtemp;
            bool kA0 = above || (kg[nt] > qA) || pad0[nt];
            bool kA1 = above || (kg[nt] + 1 > qA) || pad1[nt];
            bool kB0 = above || (kg[nt] > qB) || pad0[nt];
            bool kB1 = above || (kg[nt] + 1 > qB) || pad1[nt];
            v0 = kA0 ? v0 : 0.f; v1 = kA1 ? v1 : 0.f;
            v2 = kB0 ? v2 : 0.f; v3 = kB1 ? v3 : 0.f;
            sqA = fmaf(v0, v0, fmaf(v1, v1, sqA));
            sqB = fmaf(v2, v2, fmaf(v3, v3, sqB));
            const size_t oA = ((size_t)b * SS + qA) * SS + kg[nt];
            const size_t oB = ((size_t)b * SS + qB) * SS + kg[nt];
            *(uint32_t*)(g_attn_hi + oA) = packsplit_hi(v0, v1);
            *(uint32_t*)(g_attn_lo + oA) = packsplit_lo(v0, v1);
            *(uint32_t*)(g_attn_hi + oB) = packsplit_hi(v2, v3);
            *(uint32_t*)(g_attn_lo + oB) = packsplit_lo(v2, v3);
        }
        sqA += __shfl_xor_sync(0xffffffffu, sqA, 1);
        sqA += __shfl_xor_sync(0xffffffffu, sqA, 2);
        sqB += __shfl_xor_sync(0xffffffffu, sqB, 1);
        sqB += __shfl_xor_sync(0xffffffffu, sqB, 2);
        if ((lane & 3) == 0) {
            atomicAdd(&g_norm2[b * SS + qA], sqA);
            atomicAdd(&g_norm2[b * SS + qB], sqB);
        }
    }
}

// ---------------------------------------------------------------------------
// K3: v = elu(X·W^T + bias) -> bf16 hi/lo, natural [s][d] layout.
// ---------------------------------------------------------------------------
__global__ __launch_bounds__(NTHR, 2) void k_v(int h, const float* __restrict__ bias) {
    const int m0 = blockIdx.y * 128, n0 = blockIdx.x * 128;
    extern __shared__ char smem[];
    const uint32_t sb = (uint32_t)__cvta_generic_to_shared(smem);

    const char* Ahi = (const char*)g_x_hi + (size_t)m0 * DD * 2;
    const char* Alo = (const char*)g_x_lo + (size_t)m0 * DD * 2;
    const char* Bhi = (const char*)g_w_hi + ((size_t)h * DD * DD + (size_t)n0 * DD) * 2;
    const char* Blo = (const char*)g_w_lo + ((size_t)h * DD * DD + (size_t)n0 * DD) * 2;
    const size_t ld2 = (size_t)DD * 2;

    float C[4][4][4];
    zeroC(C);

    ldg_128x32(sb + OFF_AH, Ahi, ld2, 0); ldg_128x32(sb + OFF_AL, Alo, ld2, 0);
    ldg_128x32(sb + OFF_BH, Bhi, ld2, 0); ldg_128x32(sb + OFF_BL, Blo, ld2, 0);
    CP_COMMIT();
    ldg_128x32(sb + ST_SZ + OFF_AH, Ahi, ld2, 32); ldg_128x32(sb + ST_SZ + OFF_AL, Alo, ld2, 32);
    ldg_128x32(sb + ST_SZ + OFF_BH, Bhi, ld2, 32); ldg_128x32(sb + ST_SZ + OFF_BL, Blo, ld2, 32);
    CP_COMMIT();
    for (int ci = 0; ci < 16; ci++) {
        if (ci + 1 < 16) CP_WAIT1(); else CP_WAIT0();
        __syncthreads();
        compute_chunk<false>(sb + (ci & 1) * ST_SZ, C);
        __syncthreads();
        if (ci + 2 < 16) {
            uint32_t d = sb + (ci & 1) * ST_SZ;
            int kt = (ci + 2) * 32;
            ldg_128x32(d + OFF_AH, Ahi, ld2, kt); ldg_128x32(d + OFF_AL, Alo, ld2, kt);
            ldg_128x32(d + OFF_BH, Bhi, ld2, kt); ldg_128x32(d + OFF_BL, Blo, ld2, kt);
            CP_COMMIT();
        }
    }

    const int lane = threadIdx.x & 31, wid = threadIdx.x >> 5;
    const int wm = wid >> 2, wn = wid & 3;

    float b0[4], b1[4]; int col[4];
#pragma unroll
    for (int nt = 0; nt < 4; nt++) {
        col[nt] = n0 + wn * 32 + nt * 8 + (lane & 3) * 2;
        b0[nt] = __ldg(bias + col[nt]);
        b1[nt] = __ldg(bias + col[nt] + 1);
    }
#pragma unroll
    for (int mt = 0; mt < 4; mt++) {
        const int r0 = wm * 64 + mt * 16 + (lane >> 2);
        const size_t mA = (size_t)(m0 + r0), mB = mA + 8;
#pragma unroll
        for (int nt = 0; nt < 4; nt++) {
            float v0 = C[mt][nt][0] + b0[nt], v1 = C[mt][nt][1] + b1[nt];
            float v2 = C[mt][nt][2] + b0[nt], v3 = C[mt][nt][3] + b1[nt];
            v0 = (v0 > 0.f) ? v0 : expm1f(v0);
            v1 = (v1 > 0.f) ? v1 : expm1f(v1);
            v2 = (v2 > 0.f) ? v2 : expm1f(v2);
            v3 = (v3 > 0.f) ? v3 : expm1f(v3);
            const size_t oA = mA * DD + col[nt], oB = mB * DD + col[nt];
            *(uint32_t*)(g_v_hi + oA) = packsplit_hi(v0, v1);
            *(uint32_t*)(g_v_lo + oA) = packsplit_lo(v0, v1);
            *(uint32_t*)(g_v_hi + oB) = packsplit_hi(v2, v3);
            *(uint32_t*)(g_v_lo + oB) = packsplit_lo(v2, v3);
        }
    }
}

// ---------------------------------------------------------------------------
// K4: xnew = invnorm * (attn · v); B via ldmatrix.trans on natural v layout.
//     Skips all-zero attn k-chunks (below diagonal, no pad).
// ---------------------------------------------------------------------------
__global__ __launch_bounds__(NTHR, 2) void k_av(float* __restrict__ out) {
    const int b = blockIdx.z, q0 = blockIdx.y * 128, n0 = blockIdx.x * 128;
    extern __shared__ char smem[];
    const uint32_t sb = (uint32_t)__cvta_generic_to_shared(smem);

    const char* Ahi = (const char*)g_attn_hi + ((size_t)b * SS + q0) * SS * 2;
    const char* Alo = (const char*)g_attn_lo + ((size_t)b * SS + q0) * SS * 2;
    const char* Bhi = (const char*)g_v_hi + ((size_t)b * SS * DD + n0) * 2;
    const char* Blo = (const char*)g_v_lo + ((size_t)b * SS * DD + n0) * 2;
    const size_t lda2 = (size_t)SS * 2, ldb2 = (size_t)DD * 2;
    const int* p32 = g_pad32 + b * (SS / 32);

    float C[4][4][4];
    zeroC(C);

    // chunk iterator with skip
    int kt_a = 0;
    while (kt_a + 32 <= q0 && !p32[kt_a >> 5]) kt_a += 32;
    int kt_b = kt_a + 32;
    while (kt_b < SS && kt_b + 32 <= q0 && !p32[kt_b >> 5]) kt_b += 32;

    ldg_128x32(sb + OFF_AH, Ahi, lda2, kt_a); ldg_128x32(sb + OFF_AL, Alo, lda2, kt_a);
    ldg_32x128(sb + OFF_BH, Bhi, ldb2, kt_a); ldg_32x128(sb + OFF_BL, Blo, ldb2, kt_a);
    CP_COMMIT();
    bool has_b = (kt_b < SS);
    if (has_b) {
        ldg_128x32(sb + ST_SZ + OFF_AH, Ahi, lda2, kt_b); ldg_128x32(sb + ST_SZ + OFF_AL, Alo, lda2, kt_b);
        ldg_32x128(sb + ST_SZ + OFF_BH, Bhi, ldb2, kt_b); ldg_32x128(sb + ST_SZ + OFF_BL, Blo, ldb2, kt_b);
        CP_COMMIT();
    }
    int stage = 0;
    while (true) {
        if (has_b) CP_WAIT1(); else CP_WAIT0();
        __syncthreads();
        compute_chunk<true>(sb + stage * ST_SZ, C);
        __syncthreads();
        if (!has_b) break;
        int kt_c = kt_b + 32;
        while (kt_c < SS && kt_c + 32 <= q0 && !p32[kt_c >> 5]) kt_c += 32;
        bool has_c = (kt_c < SS);
        if (has_c) {
            uint32_t d = sb + stage * ST_SZ;
            ldg_128x32(d + OFF_AH, Ahi, lda2, kt_c); ldg_128x32(d + OFF_AL, Alo, lda2, kt_c);
            ldg_32x128(d + OFF_BH, Bhi, ldb2, kt_c); ldg_32x128(d + OFF_BL, Blo, ldb2, kt_c);
            CP_COMMIT();
        }
        stage ^= 1;
        kt_b = kt_c;
        has_b = has_c;
    }

    const int lane = threadIdx.x & 31, wid = threadIdx.x >> 5;
    const int wm = wid >> 2, wn = wid & 3;
#pragma unroll
    for (int mt = 0; mt < 4; mt++) {
        const int r0 = wm * 64 + mt * 16 + (lane >> 2);
        const int qA = q0 + r0, qB = qA + 8;
        const float invA = 1.f / fmaxf(sqrtf(g_norm2[b * SS + qA]), 1e-5f);
        const float invB = 1.f / fmaxf(sqrtf(g_norm2[b * SS + qB]), 1e-5f);
#pragma unroll
        for (int nt = 0; nt < 4; nt++) {
            const int col = n0 + wn * 32 + nt * 8 + (lane & 3) * 2;
            float v0 = C[mt][nt][0] * invA, v1 = C[mt][nt][1] * invA;
            float v2 = C[mt][nt][2] * invB, v3 = C[mt][nt][3] * invB;
            const size_t oA = ((size_t)b * SS + qA) * DD + col;
            const size_t oB = ((size_t)b * SS + qB) * DD + col;
            *(uint32_t*)(g_x_hi + oA) = packsplit_hi(v0, v1);
            *(uint32_t*)(g_x_lo + oA) = packsplit_lo(v0, v1);
            *(uint32_t*)(g_x_hi + oB) = packsplit_hi(v2, v3);
            *(uint32_t*)(g_x_lo + oB) = packsplit_lo(v2, v3);
            float2* opA = (float2*)(out + oA);
            float2* opB = (float2*)(out + oB);
            float2 a = *opA; a.x += v0; a.y += v1; *opA = a;
            float2 c = *opB; c.x += v2; c.y += v3; *opB = c;
        }
    }
}

// ---------------------------------------------------------------------------
// utility kernels
// ---------------------------------------------------------------------------
__global__ void k_split_x(const float* __restrict__ in) {
    size_t i = (size_t)blockIdx.x * NTHR + threadIdx.x;
    float v = in[i];
    __nv_bfloat16 h = __float2bfloat16(v);
    g_x_hi[i] = h;
    g_x_lo[i] = __float2bfloat16(v - __bfloat162float(h));
}
__global__ void k_split_w(const float* __restrict__ w) {
    size_t i = (size_t)blockIdx.x * NTHR + threadIdx.x;
    float v = w[i];
    __nv_bfloat16 h = __float2bfloat16(v);
    g_w_hi[i] = h;
    g_w_lo[i] = __float2bfloat16(v - __bfloat162float(h));
}
__global__ void k_zero_out(float4* out) {
    out[(size_t)blockIdx.x * NTHR + threadIdx.x] = make_float4(0.f, 0.f, 0.f, 0.f);
}
__global__ void k_zero_norm() {
    int i = blockIdx.x * NTHR + threadIdx.x;
    if (i < BB * SS) g_norm2[i] = 0.f;
}
__global__ void k_flags32(const int* __restrict__ et) {
    int idx = blockIdx.x * blockDim.x + threadIdx.x;  // BB*32 = 512
    if (idx < BB * (SS / 32)) {
        int b = idx >> 5, cc = idx & 31;
        int any = 0;
        for (int i = 0; i < 32; i++) any |= (et[b * SS + cc * 32 + i] == 0);
        g_pad32[idx] = any;
    }
}
__global__ void k_flags128() {
    int idx = threadIdx.x;  // BB*8 = 128
    if (idx < BB * 8) {
        int b = idx >> 3, kb = idx & 7;
        int any = 0;
        for (int c = 0; c < 4; c++) any |= g_pad32[b * 32 + kb * 4 + c];
        g_padblk[idx] = any;
    }
}

// ---------------------------------------------------------------------------
extern "C" void kernel_launch(void* const* d_in, const int* in_sizes, int n_in,
                              void* d_out, int out_size) {
    const float* x_in = (const float*)d_in[0];   // [B,S,D] fp32
    const int* et = (const int*)d_in[2];         // [B,S] int32
    const float* W = (const float*)d_in[3];      // [H,D,D] fp32
    const float* bias = (const float*)d_in[4];   // [H,D] fp32
    float* out = (float*)d_out;

    static int configured = 0;
    if (!configured) {
        cudaFuncSetAttribute(k_qk, cudaFuncAttributeMaxDynamicSharedMemorySize, SMEM_SZ);
        cudaFuncSetAttribute(k_v,  cudaFuncAttributeMaxDynamicSharedMemorySize, SMEM_SZ);
        cudaFuncSetAttribute(k_av, cudaFuncAttributeMaxDynamicSharedMemorySize, SMEM_SZ);
        configured = 1;
    }

    k_split_x<<<32768, NTHR>>>(x_in);     // 8.4M elems
    k_split_w<<<4096, NTHR>>>(W);         // 1.05M elems
    k_zero_out<<<8192, NTHR>>>((float4*)out);
    k_flags32<<<2, 256>>>(et);
    k_flags128<<<1, 128>>>();

    const dim3 grid_qk(8, 8, BB);
    const dim3 grid_v(4, 128);
    const dim3 grid_av(4, 8, BB);

    for (int h = 0; h < HH; h++) {
        k_zero_norm<<<64, NTHR>>>();
        k_qk<<<grid_qk, NTHR, SMEM_SZ>>>(et);
        k_v<<<grid_v, NTHR, SMEM_SZ>>>(h, bias + (size_t)h * DD);
        k_av<<<grid_av, NTHR, SMEM_SZ>>>(out);
    }
}

// round 10
// speedup vs baseline: 3.2812x; 1.0720x over previous
#include <cuda_runtime.h>
#include <cuda_bf16.h>
#include <math.h>
#include <stdint.h>

// Problem constants
#define BB 16
#define SS 1024
#define DD 512
#define HH 4
#define NTHR 256

// smem staging: per stage 4 tiles (A hi/lo 128x(32+8)bf16, B hi/lo)
#define ST_SZ  40960
#define OFF_AH 0
#define OFF_AL 10240
#define OFF_BH 20480
#define OFF_BL 30720
#define SMEM_SZ (2 * ST_SZ)

#define STRA 80    // bytes per A/B-NT smem row (40 bf16)
#define STRB 272   // bytes per B-NN smem row (136 bf16)

// ---------------- device scratch ----------------
__device__ __align__(16) __nv_bfloat16 g_x_hi[(size_t)BB*SS*DD];
__device__ __align__(16) __nv_bfloat16 g_x_lo[(size_t)BB*SS*DD];
__device__ __align__(16) __nv_bfloat16 g_v_hi[(size_t)BB*SS*DD];
__device__ __align__(16) __nv_bfloat16 g_v_lo[(size_t)BB*SS*DD];
__device__ __align__(16) __nv_bfloat16 g_attn_hi[(size_t)BB*SS*SS];
__device__ __align__(16) __nv_bfloat16 g_attn_lo[(size_t)BB*SS*SS];
__device__ __align__(16) __nv_bfloat16 g_w_hi[(size_t)HH*DD*DD];
__device__ __align__(16) __nv_bfloat16 g_w_lo[(size_t)HH*DD*DD];
__device__ __align__(16) float g_norm2[HH * BB * SS];   // per-head, zeroed once
__device__ int g_pad32[BB*(SS/32)];
__device__ int g_padblk[BB*(SS/128)];

// ---------------- PTX helpers (sm_80-level only; harness targets plain sm_103) ----
#define CPA16(s, g) asm volatile("cp.async.cg.shared.global [%0], [%1], 16;" :: "r"(s), "l"(g))
#define CP_COMMIT() asm volatile("cp.async.commit_group;" ::: "memory")
#define CP_WAIT1()  asm volatile("cp.async.wait_group 1;" ::: "memory")
#define CP_WAIT0()  asm volatile("cp.async.wait_group 0;" ::: "memory")

#define LDSMX4(r0, r1, r2, r3, a)                                              \
    asm volatile("ldmatrix.sync.aligned.m8n8.x4.shared.b16 {%0,%1,%2,%3}, [%4];" \
                 : "=r"(r0), "=r"(r1), "=r"(r2), "=r"(r3) : "r"(a))
#define LDSMX4T(r0, r1, r2, r3, a)                                             \
    asm volatile("ldmatrix.sync.aligned.m8n8.x4.trans.shared.b16 {%0,%1,%2,%3}, [%4];" \
                 : "=r"(r0), "=r"(r1), "=r"(r2), "=r"(r3) : "r"(a))

#define MMA16816(c, a, b0v, b1v)                                               \
    asm volatile(                                                              \
        "mma.sync.aligned.m16n8k16.row.col.f32.bf16.bf16.f32 "                 \
        "{%0,%1,%2,%3}, {%4,%5,%6,%7}, {%8,%9}, {%0,%1,%2,%3};"                \
        : "+f"((c)[0]), "+f"((c)[1]), "+f"((c)[2]), "+f"((c)[3])               \
        : "r"((a)[0]), "r"((a)[1]), "r"((a)[2]), "r"((a)[3]), "r"(b0v), "r"(b1v))

// ---------------- tile loaders (256 threads) ----------------
__device__ __forceinline__ void ldg_128x32(uint32_t dst, const char* src, size_t ld2, int kt) {
#pragma unroll
    for (int p = 0; p < 2; p++) {
        int i = threadIdx.x + p * NTHR;
        int row = i >> 2, seg = i & 3;
        CPA16(dst + row * STRA + seg * 16,
              src + (size_t)row * ld2 + (size_t)kt * 2 + seg * 16);
    }
}
__device__ __forceinline__ void ldg_32x128(uint32_t dst, const char* src, size_t ld2, int kt) {
#pragma unroll
    for (int p = 0; p < 2; p++) {
        int i = threadIdx.x + p * NTHR;
        int row = i >> 4, seg = i & 15;
        CPA16(dst + row * STRB + seg * 16,
              src + (size_t)(kt + row) * ld2 + seg * 16);
    }
}

// ---------------- warp MMA compute on one staged 128x128x32 chunk ------------
template <bool BT>
__device__ __forceinline__ void compute_chunk(uint32_t sbase, float (&C)[4][4][4]) {
    const int lane = threadIdx.x & 31;
    const int wid = threadIdx.x >> 5;
    const int wm = wid >> 2, wn = wid & 3;
#pragma unroll
    for (int ks = 0; ks < 2; ks++) {
        uint32_t ah[4][4], al[4][4];
#pragma unroll
        for (int mt = 0; mt < 4; mt++) {
            uint32_t ra = sbase + OFF_AH +
                (uint32_t)((wm * 64 + mt * 16 + (lane & 15)) * STRA + ks * 32 + (lane >> 4) * 16);
            LDSMX4(ah[mt][0], ah[mt][1], ah[mt][2], ah[mt][3], ra);
            ra += (OFF_AL - OFF_AH);
            LDSMX4(al[mt][0], al[mt][1], al[mt][2], al[mt][3], ra);
        }
        uint32_t bh[2][4], bl[2][4];
#pragma unroll
        for (int ntp = 0; ntp < 2; ntp++) {
            if (!BT) {
                uint32_t rb = sbase + OFF_BH +
                    (uint32_t)((wn * 32 + ntp * 16 + (lane >> 4) * 8 + (lane & 7)) * STRA +
                               ks * 32 + ((lane >> 3) & 1) * 16);
                LDSMX4(bh[ntp][0], bh[ntp][1], bh[ntp][2], bh[ntp][3], rb);
                rb += (OFF_BL - OFF_BH);
                LDSMX4(bl[ntp][0], bl[ntp][1], bl[ntp][2], bl[ntp][3], rb);
            } else {
                uint32_t rb = sbase + OFF_BH +
                    (uint32_t)((ks * 16 + ((lane >> 3) & 1) * 8 + (lane & 7)) * STRB +
                               (wn * 32 + ntp * 16) * 2 + (lane >> 4) * 16);
                LDSMX4T(bh[ntp][0], bh[ntp][1], bh[ntp][2], bh[ntp][3], rb);
                rb += (OFF_BL - OFF_BH);
                LDSMX4T(bl[ntp][0], bl[ntp][1], bl[ntp][2], bl[ntp][3], rb);
            }
        }
#pragma unroll
        for (int mt = 0; mt < 4; mt++)
#pragma unroll
            for (int nt = 0; nt < 4; nt++) {
                const int p = nt >> 1, j = (nt & 1) * 2;
                MMA16816(C[mt][nt], ah[mt], bh[p][j], bh[p][j + 1]);
                MMA16816(C[mt][nt], ah[mt], bl[p][j], bl[p][j + 1]);
                MMA16816(C[mt][nt], al[mt], bh[p][j], bh[p][j + 1]);
            }
    }
}

__device__ __forceinline__ void zeroC(float (&C)[4][4][4]) {
#pragma unroll
    for (int a = 0; a < 4; a++)
#pragma unroll
        for (int b = 0; b < 4; b++)
#pragma unroll
            for (int c = 0; c < 4; c++) C[a][b][c] = 0.f;
}
__device__ __forceinline__ uint32_t packsplit_hi(float v0, float v1) {
    __nv_bfloat162 h = __floats2bfloat162_rn(v0, v1);
    return *(uint32_t*)&h;
}
__device__ __forceinline__ uint32_t packsplit_lo(float v0, float v1) {
    float r0 = v0 - __bfloat162float(__float2bfloat16(v0));
    float r1 = v1 - __bfloat162float(__float2bfloat16(v1));
    __nv_bfloat162 l = __floats2bfloat162_rn(r0, r1);
    return *(uint32_t*)&l;
}

// dense-K 16-chunk double-buffered mainloop (both operands NT 128x32 tiles)
__device__ __forceinline__ void mainloop_dense(uint32_t sb,
                                               const char* Ahi, const char* Alo,
                                               const char* Bhi, const char* Blo,
                                               size_t ld2, float (&C)[4][4][4]) {
    ldg_128x32(sb + OFF_AH, Ahi, ld2, 0); ldg_128x32(sb + OFF_AL, Alo, ld2, 0);
    ldg_128x32(sb + OFF_BH, Bhi, ld2, 0); ldg_128x32(sb + OFF_BL, Blo, ld2, 0);
    CP_COMMIT();
    ldg_128x32(sb + ST_SZ + OFF_AH, Ahi, ld2, 32); ldg_128x32(sb + ST_SZ + OFF_AL, Alo, ld2, 32);
    ldg_128x32(sb + ST_SZ + OFF_BH, Bhi, ld2, 32); ldg_128x32(sb + ST_SZ + OFF_BL, Blo, ld2, 32);
    CP_COMMIT();
    for (int ci = 0; ci < 16; ci++) {
        if (ci + 1 < 16) CP_WAIT1(); else CP_WAIT0();
        __syncthreads();
        compute_chunk<false>(sb + (ci & 1) * ST_SZ, C);
        __syncthreads();
        if (ci + 2 < 16) {
            uint32_t d = sb + (ci & 1) * ST_SZ;
            int kt = (ci + 2) * 32;
            ldg_128x32(d + OFF_AH, Ahi, ld2, kt); ldg_128x32(d + OFF_AL, Alo, ld2, kt);
            ldg_128x32(d + OFF_BH, Bhi, ld2, kt); ldg_128x32(d + OFF_BL, Blo, ld2, kt);
            CP_COMMIT();
        }
    }
}

// ---------------------------------------------------------------------------
// Fused K1+K3: blocks [0,1024) do qk tiles, blocks [1024,1536) do v tiles.
// Both depend only on head input x; co-scheduling removes a kernel boundary.
// ---------------------------------------------------------------------------
__global__ __launch_bounds__(NTHR, 2) void k_qkv(int h, const int* __restrict__ et,
                                                 const float* __restrict__ bias) {
    extern __shared__ char smem[];
    const uint32_t sb = (uint32_t)__cvta_generic_to_shared(smem);
    const int flat = blockIdx.x;
    const int lane = threadIdx.x & 31, wid = threadIdx.x >> 5;
    const int wm = wid >> 2, wn = wid & 3;
    const size_t ld2 = (size_t)DD * 2;

    if (flat < 1024) {
        // ---------------- qk path ----------------
        const int b = flat >> 6, qi = (flat >> 3) & 7, ki = flat & 7;
        const int q0 = qi * 128, k0 = ki * 128;
        const bool below = (k0 < q0);
        if (below && !g_padblk[b * 8 + ki]) return;
        const bool above = (k0 > q0);

        const char* Ahi = (const char*)g_x_hi + ((size_t)b * SS + q0) * DD * 2;
        const char* Alo = (const char*)g_x_lo + ((size_t)b * SS + q0) * DD * 2;
        const char* Bhi = (const char*)g_x_hi + ((size_t)b * SS + k0) * DD * 2;
        const char* Blo = (const char*)g_x_lo + ((size_t)b * SS + k0) * DD * 2;

        float C[4][4][4];
        zeroC(C);
        mainloop_dense(sb, Ahi, Alo, Bhi, Blo, ld2, C);

        const float invtemp = 0.04419417382415922f;  // 1/sqrt(512)
        float* norm2 = g_norm2 + (size_t)h * BB * SS;

        int kg[4]; bool pad0[4], pad1[4];
#pragma unroll
        for (int nt = 0; nt < 4; nt++) {
            kg[nt] = k0 + wn * 32 + nt * 8 + (lane & 3) * 2;
            pad0[nt] = (__ldg(et + b * SS + kg[nt]) == 0);
            pad1[nt] = (__ldg(et + b * SS + kg[nt] + 1) == 0);
        }
#pragma unroll
        for (int mt = 0; mt < 4; mt++) {
            const int r0 = wm * 64 + mt * 16 + (lane >> 2);
            const int qA = q0 + r0, qB = q0 + r0 + 8;
            float sqA = 0.f, sqB = 0.f;
#pragma unroll
            for (int nt = 0; nt < 4; nt++) {
                float v0 = C[mt][nt][0] * invtemp, v1 = C[mt][nt][1] * invtemp;
                float v2 = C[mt][nt][2] * invtemp, v3 = C[mt][nt][3] * invtemp;
                bool kA0 = above || (kg[nt] > qA) || pad0[nt];
                bool kA1 = above || (kg[nt] + 1 > qA) || pad1[nt];
                bool kB0 = above || (kg[nt] > qB) || pad0[nt];
                bool kB1 = above || (kg[nt] + 1 > qB) || pad1[nt];
                v0 = kA0 ? v0 : 0.f; v1 = kA1 ? v1 : 0.f;
                v2 = kB0 ? v2 : 0.f; v3 = kB1 ? v3 : 0.f;
                sqA = fmaf(v0, v0, fmaf(v1, v1, sqA));
                sqB = fmaf(v2, v2, fmaf(v3, v3, sqB));
                const size_t oA = ((size_t)b * SS + qA) * SS + kg[nt];
                const size_t oB = ((size_t)b * SS + qB) * SS + kg[nt];
                *(uint32_t*)(g_attn_hi + oA) = packsplit_hi(v0, v1);
                *(uint32_t*)(g_attn_lo + oA) = packsplit_lo(v0, v1);
                *(uint32_t*)(g_attn_hi + oB) = packsplit_hi(v2, v3);
                *(uint32_t*)(g_attn_lo + oB) = packsplit_lo(v2, v3);
            }
            sqA += __shfl_xor_sync(0xffffffffu, sqA, 1);
            sqA += __shfl_xor_sync(0xffffffffu, sqA, 2);
            sqB += __shfl_xor_sync(0xffffffffu, sqB, 1);
            sqB += __shfl_xor_sync(0xffffffffu, sqB, 2);
            if ((lane & 3) == 0) {
                atomicAdd(&norm2[b * SS + qA], sqA);
                atomicAdd(&norm2[b * SS + qB], sqB);
            }
        }
    } else {
        // ---------------- v path ----------------
        const int f = flat - 1024;           // 0..511
        const int m0 = (f >> 2) * 128, n0 = (f & 3) * 128;

        const char* Ahi = (const char*)g_x_hi + (size_t)m0 * DD * 2;
        const char* Alo = (const char*)g_x_lo + (size_t)m0 * DD * 2;
        const char* Bhi = (const char*)g_w_hi + ((size_t)h * DD * DD + (size_t)n0 * DD) * 2;
        const char* Blo = (const char*)g_w_lo + ((size_t)h * DD * DD + (size_t)n0 * DD) * 2;

        float C[4][4][4];
        zeroC(C);
        mainloop_dense(sb, Ahi, Alo, Bhi, Blo, ld2, C);

        float b0[4], b1[4]; int col[4];
#pragma unroll
        for (int nt = 0; nt < 4; nt++) {
            col[nt] = n0 + wn * 32 + nt * 8 + (lane & 3) * 2;
            b0[nt] = __ldg(bias + col[nt]);
            b1[nt] = __ldg(bias + col[nt] + 1);
        }
#pragma unroll
        for (int mt = 0; mt < 4; mt++) {
            const int r0 = wm * 64 + mt * 16 + (lane >> 2);
            const size_t mA = (size_t)(m0 + r0), mB = mA + 8;
#pragma unroll
            for (int nt = 0; nt < 4; nt++) {
                float v0 = C[mt][nt][0] + b0[nt], v1 = C[mt][nt][1] + b1[nt];
                float v2 = C[mt][nt][2] + b0[nt], v3 = C[mt][nt][3] + b1[nt];
                v0 = (v0 > 0.f) ? v0 : expm1f(v0);
                v1 = (v1 > 0.f) ? v1 : expm1f(v1);
                v2 = (v2 > 0.f) ? v2 : expm1f(v2);
                v3 = (v3 > 0.f) ? v3 : expm1f(v3);
                const size_t oA = mA * DD + col[nt], oB = mB * DD + col[nt];
                *(uint32_t*)(g_v_hi + oA) = packsplit_hi(v0, v1);
                *(uint32_t*)(g_v_lo + oA) = packsplit_lo(v0, v1);
                *(uint32_t*)(g_v_hi + oB) = packsplit_hi(v2, v3);
                *(uint32_t*)(g_v_lo + oB) = packsplit_lo(v2, v3);
            }
        }
    }
}

// ---------------------------------------------------------------------------
// K4: xnew = invnorm * (attn · v); B via ldmatrix.trans on natural v layout.
// ---------------------------------------------------------------------------
__global__ __launch_bounds__(NTHR, 2) void k_av(int h, float* __restrict__ out) {
    const int b = blockIdx.z, q0 = blockIdx.y * 128, n0 = blockIdx.x * 128;
    extern __shared__ char smem[];
    const uint32_t sb = (uint32_t)__cvta_generic_to_shared(smem);

    const char* Ahi = (const char*)g_attn_hi + ((size_t)b * SS + q0) * SS * 2;
    const char* Alo = (const char*)g_attn_lo + ((size_t)b * SS + q0) * SS * 2;
    const char* Bhi = (const char*)g_v_hi + ((size_t)b * SS * DD + n0) * 2;
    const char* Blo = (const char*)g_v_lo + ((size_t)b * SS * DD + n0) * 2;
    const size_t lda2 = (size_t)SS * 2, ldb2 = (size_t)DD * 2;
    const int* p32 = g_pad32 + b * (SS / 32);

    float C[4][4][4];
    zeroC(C);

    int kt_a = 0;
    while (kt_a + 32 <= q0 && !p32[kt_a >> 5]) kt_a += 32;
    int kt_b = kt_a + 32;
    while (kt_b < SS && kt_b + 32 <= q0 && !p32[kt_b >> 5]) kt_b += 32;

    ldg_128x32(sb + OFF_AH, Ahi, lda2, kt_a); ldg_128x32(sb + OFF_AL, Alo, lda2, kt_a);
    ldg_32x128(sb + OFF_BH, Bhi, ldb2, kt_a); ldg_32x128(sb + OFF_BL, Blo, ldb2, kt_a);
    CP_COMMIT();
    bool has_b = (kt_b < SS);
    if (has_b) {
        ldg_128x32(sb + ST_SZ + OFF_AH, Ahi, lda2, kt_b); ldg_128x32(sb + ST_SZ + OFF_AL, Alo, lda2, kt_b);
        ldg_32x128(sb + ST_SZ + OFF_BH, Bhi, ldb2, kt_b); ldg_32x128(sb + ST_SZ + OFF_BL, Blo, ldb2, kt_b);
        CP_COMMIT();
    }
    int stage = 0;
    while (true) {
        if (has_b) CP_WAIT1(); else CP_WAIT0();
        __syncthreads();
        compute_chunk<true>(sb + stage * ST_SZ, C);
        __syncthreads();
        if (!has_b) break;
        int kt_c = kt_b + 32;
        while (kt_c < SS && kt_c + 32 <= q0 && !p32[kt_c >> 5]) kt_c += 32;
        bool has_c = (kt_c < SS);
        if (has_c) {
            uint32_t d = sb + stage * ST_SZ;
            ldg_128x32(d + OFF_AH, Ahi, lda2, kt_c); ldg_128x32(d + OFF_AL, Alo, lda2, kt_c);
            ldg_32x128(d + OFF_BH, Bhi, ldb2, kt_c); ldg_32x128(d + OFF_BL, Blo, ldb2, kt_c);
            CP_COMMIT();
        }
        stage ^= 1;
        kt_b = kt_c;
        has_b = has_c;
    }

    const int lane = threadIdx.x & 31, wid = threadIdx.x >> 5;
    const int wm = wid >> 2, wn = wid & 3;
    const float* norm2 = g_norm2 + (size_t)h * BB * SS;
#pragma unroll
    for (int mt = 0; mt < 4; mt++) {
        const int r0 = wm * 64 + mt * 16 + (lane >> 2);
        const int qA = q0 + r0, qB = qA + 8;
        const float invA = 1.f / fmaxf(sqrtf(norm2[b * SS + qA]), 1e-5f);
        const float invB = 1.f / fmaxf(sqrtf(norm2[b * SS + qB]), 1e-5f);
#pragma unroll
        for (int nt = 0; nt < 4; nt++) {
            const int col = n0 + wn * 32 + nt * 8 + (lane & 3) * 2;
            float v0 = C[mt][nt][0] * invA, v1 = C[mt][nt][1] * invA;
            float v2 = C[mt][nt][2] * invB, v3 = C[mt][nt][3] * invB;
            const size_t oA = ((size_t)b * SS + qA) * DD + col;
            const size_t oB = ((size_t)b * SS + qB) * DD + col;
            *(uint32_t*)(g_x_hi + oA) = packsplit_hi(v0, v1);
            *(uint32_t*)(g_x_lo + oA) = packsplit_lo(v0, v1);
            *(uint32_t*)(g_x_hi + oB) = packsplit_hi(v2, v3);
            *(uint32_t*)(g_x_lo + oB) = packsplit_lo(v2, v3);
            float2* opA = (float2*)(out + oA);
            float2* opB = (float2*)(out + oB);
            float2 a = *opA; a.x += v0; a.y += v1; *opA = a;
            float2 c = *opB; c.x += v2; c.y += v3; *opB = c;
        }
    }
}

// ---------------------------------------------------------------------------
// utility kernels
// ---------------------------------------------------------------------------
__global__ void k_split_x(const float* __restrict__ in) {
    size_t i = (size_t)blockIdx.x * NTHR + threadIdx.x;
    float v = in[i];
    __nv_bfloat16 h = __float2bfloat16(v);
    g_x_hi[i] = h;
    g_x_lo[i] = __float2bfloat16(v - __bfloat162float(h));
}
__global__ void k_split_w(const float* __restrict__ w) {
    size_t i = (size_t)blockIdx.x * NTHR + threadIdx.x;
    float v = w[i];
    __nv_bfloat16 h = __float2bfloat16(v);
    g_w_hi[i] = h;
    g_w_lo[i] = __float2bfloat16(v - __bfloat162float(h));
}
__global__ void k_zero_out(float4* out) {
    size_t i = (size_t)blockIdx.x * NTHR + threadIdx.x;
    out[i] = make_float4(0.f, 0.f, 0.f, 0.f);
    if (i < (HH * BB * SS) / 4)
        ((float4*)g_norm2)[i] = make_float4(0.f, 0.f, 0.f, 0.f);
}
__global__ void k_flags32(const int* __restrict__ et) {
    int idx = blockIdx.x * blockDim.x + threadIdx.x;  // BB*32 = 512
    if (idx < BB * (SS / 32)) {
        int b = idx >> 5, cc = idx & 31;
        int any = 0;
        for (int i = 0; i < 32; i++) any |= (et[b * SS + cc * 32 + i] == 0);
        g_pad32[idx] = any;
    }
}
__global__ void k_flags128() {
    int idx = threadIdx.x;  // BB*8 = 128
    if (idx < BB * 8) {
        int b = idx >> 3, kb = idx & 7;
        int any = 0;
        for (int c = 0; c < 4; c++) any |= g_pad32[b * 32 + kb * 4 + c];
        g_padblk[idx] = any;
    }
}

// ---------------------------------------------------------------------------
extern "C" void kernel_launch(void* const* d_in, const int* in_sizes, int n_in,
                              void* d_out, int out_size) {
    const float* x_in = (const float*)d_in[0];   // [B,S,D] fp32
    const int* et = (const int*)d_in[2];         // [B,S] int32
    const float* W = (const float*)d_in[3];      // [H,D,D] fp32
    const float* bias = (const float*)d_in[4];   // [H,D] fp32
    float* out = (float*)d_out;

    static int configured = 0;
    if (!configured) {
        cudaFuncSetAttribute(k_qkv, cudaFuncAttributeMaxDynamicSharedMemorySize, SMEM_SZ);
        cudaFuncSetAttribute(k_av,  cudaFuncAttributeMaxDynamicSharedMemorySize, SMEM_SZ);
        configured = 1;
    }

    // 5 setup launches; launch #6 (first big kernel) is what ncu -s 5 -c 1 captures
    k_split_x<<<32768, NTHR>>>(x_in);     // 8.4M elems
    k_split_w<<<4096, NTHR>>>(W);         // 1.05M elems
    k_zero_out<<<8192, NTHR>>>((float4*)out);
    k_flags32<<<2, 256>>>(et);
    k_flags128<<<1, 128>>>();

    const dim3 grid_av(4, 8, BB);
    for (int h = 0; h < HH; h++) {
        k_qkv<<<1536, NTHR, SMEM_SZ>>>(h, et, bias + (size_t)h * DD);
        k_av<<<grid_av, NTHR, SMEM_SZ>>>(h, out);
    }
}